// round 1
// baseline (speedup 1.0000x reference)
#include <cuda_runtime.h>
#include <math_constants.h>

// Problem shape (fixed for this registry entry)
#define B_  8
#define N_  2048
#define C_  64
#define H_  4
#define D_  64
#define HD_ 256          // H*D
#define NW_ (N_/32)      // mask words per row = 64
#define LOG2E 1.4426950408889634f

// ---------------- scratch (device globals: no allocation allowed) -----------
__device__ float    g_h  [B_*H_*N_*D_];   // 16 MB  per-head projected features
__device__ float    g_z  [B_*N_*HD_];     // 16 MB  concat+lrelu of layer-1 output
__device__ float    g_h2 [B_*N_*D_];      //  4 MB  second projection
__device__ unsigned g_maskT[NW_*N_];      // 512 KB transposed bitmask [w][n]

// ---------------- mask build: warp per (n, word), coalesced graph reads -----
__global__ void build_mask_kernel(const int* __restrict__ graph) {
    int gwarp = (blockIdx.x * blockDim.x + threadIdx.x) >> 5;
    int lane  = threadIdx.x & 31;
    if (gwarp >= N_ * NW_) return;
    int n = gwarp >> 6;          // / NW_
    int w = gwarp & (NW_ - 1);
    int m = w * 32 + lane;
    bool bit = (graph[(size_t)n * N_ + m] != 0) || (m == n);
    unsigned word = __ballot_sync(0xffffffffu, bit);
    if (lane == 0) g_maskT[w * N_ + n] = word;
}

// ---------------- proj1: h[b,h,n,d] = sum_c x[b,n,c] * Wh[h,d,c] ------------
__global__ void proj1_kernel(const float* __restrict__ x,
                             const float* __restrict__ Wh) {
    __shared__ float xs[64][65];
    __shared__ float ws[64][65];
    int t    = threadIdx.x;              // 256 threads
    int row0 = blockIdx.x * 64;          // flattened b*N + n
    for (int i = t; i < 64 * 64; i += 256) {
        int r = i >> 6, c = i & 63;
        xs[r][c] = x[(size_t)(row0 + r) * C_ + c];
    }
    int d0 = (t & 15) * 4;
    int r0 = (t >> 4) * 4;
    int b     = row0 >> 11;              // / N_
    int nbase = row0 & (N_ - 1);
    for (int h = 0; h < H_; ++h) {
        __syncthreads();
        for (int i = t; i < 64 * 64; i += 256) {
            int r = i >> 6, c = i & 63;
            ws[r][c] = Wh[((size_t)h * D_ + r) * C_ + c];
        }
        __syncthreads();
        float acc[4][4] = {};
        #pragma unroll 8
        for (int c = 0; c < 64; ++c) {
            float xv[4], wv[4];
            #pragma unroll
            for (int i = 0; i < 4; ++i) { xv[i] = xs[r0 + i][c]; wv[i] = ws[d0 + i][c]; }
            #pragma unroll
            for (int i = 0; i < 4; ++i)
                #pragma unroll
                for (int j = 0; j < 4; ++j)
                    acc[i][j] += xv[i] * wv[j];
        }
        #pragma unroll
        for (int i = 0; i < 4; ++i)
            #pragma unroll
            for (int j = 0; j < 4; ++j)
                g_h[(((size_t)(b * H_ + h) * N_) + nbase + r0 + i) * D_ + d0 + j] = acc[i][j];
        __syncthreads();
    }
}

// ---------------- proj2: h2[b,n,d] = sum_k z[b,n,k] * Wo[d,k] ---------------
__global__ void proj2_kernel(const float* __restrict__ Wo) {
    __shared__ float zs[64][65];
    __shared__ float ws[64][65];
    int t    = threadIdx.x;
    int row0 = blockIdx.x * 64;
    int d0 = (t & 15) * 4;
    int r0 = (t >> 4) * 4;
    float acc[4][4] = {};
    for (int kc = 0; kc < 4; ++kc) {
        __syncthreads();
        for (int i = t; i < 64 * 64; i += 256) {
            int r = i >> 6, c = i & 63;
            zs[r][c] = g_z[(size_t)(row0 + r) * HD_ + kc * 64 + c];
            ws[r][c] = Wo[(size_t)r * HD_ + kc * 64 + c];
        }
        __syncthreads();
        #pragma unroll 8
        for (int c = 0; c < 64; ++c) {
            float xv[4], wv[4];
            #pragma unroll
            for (int i = 0; i < 4; ++i) { xv[i] = zs[r0 + i][c]; wv[i] = ws[d0 + i][c]; }
            #pragma unroll
            for (int i = 0; i < 4; ++i)
                #pragma unroll
                for (int j = 0; j < 4; ++j)
                    acc[i][j] += xv[i] * wv[j];
        }
    }
    #pragma unroll
    for (int i = 0; i < 4; ++i)
        #pragma unroll
        for (int j = 0; j < 4; ++j)
            g_h2[(size_t)(row0 + r0 + i) * D_ + d0 + j] = acc[i][j];
}

// ---------------- fused masked attention (flash-style, 1 thread = 1 row) ----
// LAYER==1: src=g_h (bh = b*H+h), epilogue: +bh bias, lrelu, store to g_z (cat layout)
// LAYER==2: src=g_h2 (bh = b),    epilogue: +bo, lrelu, LayerNorm, store to out
template <int LAYER>
__global__ void __launch_bounds__(128, 3)
attn_kernel(const float* __restrict__ bias,
            const float* __restrict__ gamma,
            const float* __restrict__ beta,
            float* __restrict__ outp) {
    __shared__ float4 ksm[64][16];       // 64 rows x 64 floats (as float4)
    const int bh = blockIdx.x;
    const int n  = blockIdx.y * 128 + threadIdx.x;
    const float* hbase = (LAYER == 1 ? g_h : g_h2) + (size_t)bh * N_ * D_;

    // q row in registers
    float q[64];
    {
        const float4* qr = (const float4*)(hbase + (size_t)n * D_);
        #pragma unroll
        for (int k4 = 0; k4 < 16; ++k4) {
            float4 v = qr[k4];
            q[4*k4+0] = v.x; q[4*k4+1] = v.y; q[4*k4+2] = v.z; q[4*k4+3] = v.w;
        }
    }
    float acc[64];
    #pragma unroll
    for (int d = 0; d < 64; ++d) acc[d] = 0.f;
    float mx = -CUDART_INF_F, sum = 0.f;

    for (int tile = 0; tile < N_ / 64; ++tile) {
        __syncthreads();
        {
            const float4* src = (const float4*)(hbase + (size_t)tile * 64 * D_);
            float4* dst = (float4*)ksm;
            #pragma unroll
            for (int i = 0; i < 8; ++i) {
                int f = i * 128 + threadIdx.x;   // 0..1023 coalesced
                dst[f] = src[f];
            }
        }
        __syncthreads();
        unsigned w0 = g_maskT[(size_t)(tile * 2 + 0) * N_ + n];
        unsigned w1 = g_maskT[(size_t)(tile * 2 + 1) * N_ + n];
        #pragma unroll 1
        for (int half = 0; half < 2; ++half) {
            unsigned w = half ? w1 : w0;
            int mb = half * 32;
            #pragma unroll 1
            for (int j = 0; j < 32; ++j) {
                if ((w >> j) & 1u) {
                    int m = mb + j;
                    float s0 = 0.f, s1 = 0.f, s2 = 0.f, s3 = 0.f;
                    #pragma unroll
                    for (int k4 = 0; k4 < 16; ++k4) {
                        float4 kv = ksm[m][k4];
                        s0 += q[4*k4+0] * kv.x;
                        s1 += q[4*k4+1] * kv.y;
                        s2 += q[4*k4+2] * kv.z;
                        s3 += q[4*k4+3] * kv.w;
                    }
                    float s = (s0 + s1) + (s2 + s3);
                    if (s > mx) {
                        float f = exp2f((mx - s) * LOG2E);
                        sum *= f;
                        #pragma unroll
                        for (int d = 0; d < 64; ++d) acc[d] *= f;
                        mx = s;
                    }
                    float p = exp2f((s - mx) * LOG2E);
                    sum += p;
                    #pragma unroll
                    for (int k4 = 0; k4 < 16; ++k4) {
                        float4 kv = ksm[m][k4];
                        acc[4*k4+0] += p * kv.x;
                        acc[4*k4+1] += p * kv.y;
                        acc[4*k4+2] += p * kv.z;
                        acc[4*k4+3] += p * kv.w;
                    }
                }
            }
        }
    }

    float inv = 1.f / sum;   // diagonal always unmasked -> sum > 0

    if (LAYER == 1) {
        int h = bh & (H_ - 1);
        int b = bh >> 2;
        const float* bp = bias + h * D_;
        float* zdst = g_z + ((size_t)b * N_ + n) * HD_ + h * D_;
        #pragma unroll
        for (int k4 = 0; k4 < 16; ++k4) {
            float4 v;
            float a0 = acc[4*k4+0] * inv + bp[4*k4+0];
            float a1 = acc[4*k4+1] * inv + bp[4*k4+1];
            float a2 = acc[4*k4+2] * inv + bp[4*k4+2];
            float a3 = acc[4*k4+3] * inv + bp[4*k4+3];
            v.x = a0 > 0.f ? a0 : 0.2f * a0;
            v.y = a1 > 0.f ? a1 : 0.2f * a1;
            v.z = a2 > 0.f ? a2 : 0.2f * a2;
            v.w = a3 > 0.f ? a3 : 0.2f * a3;
            ((float4*)zdst)[k4] = v;
        }
    } else {
        // +bo, leaky relu, LayerNorm over D=64 entirely in-thread
        float mu = 0.f;
        #pragma unroll
        for (int d = 0; d < 64; ++d) {
            float v = acc[d] * inv + bias[d];
            v = v > 0.f ? v : 0.2f * v;
            acc[d] = v;
            mu += v;
        }
        mu *= (1.f / 64.f);
        float var = 0.f;
        #pragma unroll
        for (int d = 0; d < 64; ++d) {
            float t = acc[d] - mu;
            var += t * t;
        }
        var *= (1.f / 64.f);
        float rs = rsqrtf(var + 1e-5f);
        float* od = outp + ((size_t)bh * N_ + n) * D_;
        #pragma unroll
        for (int k4 = 0; k4 < 16; ++k4) {
            float4 v;
            v.x = (acc[4*k4+0] - mu) * rs * gamma[4*k4+0] + beta[4*k4+0];
            v.y = (acc[4*k4+1] - mu) * rs * gamma[4*k4+1] + beta[4*k4+1];
            v.z = (acc[4*k4+2] - mu) * rs * gamma[4*k4+2] + beta[4*k4+2];
            v.w = (acc[4*k4+3] - mu) * rs * gamma[4*k4+3] + beta[4*k4+3];
            ((float4*)od)[k4] = v;
        }
    }
}

// ---------------- launch -----------------------------------------------------
extern "C" void kernel_launch(void* const* d_in, const int* in_sizes, int n_in,
                              void* d_out, int out_size) {
    const float* x     = (const float*)d_in[0];
    const int*   graph = (const int*)  d_in[1];
    const float* Wh    = (const float*)d_in[2];
    const float* bh    = (const float*)d_in[3];
    const float* Wo    = (const float*)d_in[4];
    const float* bo    = (const float*)d_in[5];
    const float* gamma = (const float*)d_in[6];
    const float* beta  = (const float*)d_in[7];
    float* out = (float*)d_out;

    // mask: N*NW warps, 8 warps/block
    build_mask_kernel<<<(N_ * NW_) / 8, 256>>>(graph);
    // per-head projection: 16384 rows / 64 per block
    proj1_kernel<<<(B_ * N_) / 64, 256>>>(x, Wh);
    // layer-1 masked attention + bias + lrelu + cat -> g_z
    attn_kernel<1><<<dim3(B_ * H_, N_ / 128), 128>>>(bh, nullptr, nullptr, nullptr);
    // output projection -> g_h2
    proj2_kernel<<<(B_ * N_) / 64, 256>>>(Wo);
    // layer-2 masked attention + bias + lrelu + LayerNorm -> out
    attn_kernel<2><<<dim3(B_, N_ / 128), 128>>>(bo, gamma, beta, out);
}